// round 15
// baseline (speedup 1.0000x reference)
#include <cuda_runtime.h>
#include <cuda_fp16.h>
#include <cstdint>

#define N_Q   50000
#define M_S   50000
#define KNNB  32
#define KPN   15
#define CIN   64
#define COUT  128
#define KDIM  (KPN * CIN)      // 960
#define KP_EXT_INV (1.0f / 1.2f)

#define NSEG     5
#define SEG_TILE 80
#define BM       128
#define SEG_ROWS (SEG_TILE * BM)        // 10240
#define M_PAD2   (NSEG * SEG_ROWS)      // 51200

#define WCONV_BLKS ((KDIM * COUT) / 4 / 256)   // 120 blocks — exact cover

// Scratch (zero-initialized device globals; padding rows never written)
__device__ __align__(1024) __half g_kf16[(size_t)M_PAD2 * KDIM];  // A [m][k]
__device__ __align__(1024) __half g_wt16[KDIM * COUT];            // W [k][n]
__device__ float g_inv[M_PAD2];
__device__ float g_rs[M_S];

// ---------------------------------------------------------------------------
// k0: blocks 0..390: rowsum of s_feats (2 threads/row, float4 MLP=8)
//     blocks 391..510: W -> fp16 [k][n] (exactly 960*128 elements)
// ---------------------------------------------------------------------------
__global__ __launch_bounds__(256) void k0_prep(
    const float* __restrict__ sf, const float* __restrict__ W)
{
    int b = blockIdx.x;
    if (b < 391) {
        int tid = threadIdx.x;
        int row = b * 128 + (tid >> 1);
        int part = tid & 1;
        if (row < M_S) {
            const float4* p = (const float4*)&sf[(size_t)row * CIN + part * 32];
            float s = 0.0f;
            #pragma unroll
            for (int i = 0; i < 8; i++) {
                float4 v = p[i];
                s += (v.x + v.y) + (v.z + v.w);
            }
            s += __shfl_xor_sync(0xffffffffu, s, 1);
            if (part == 0) g_rs[row] = s;
        }
    } else {
        int idx = ((b - 391) * 256 + threadIdx.x) * 4;   // < 960*128 exactly
        float4 v = *(const float4*)&W[idx];
        __half2 h0 = __floats2half2_rn(v.x, v.y);
        __half2 h1 = __floats2half2_rn(v.z, v.w);
        *reinterpret_cast<uint2*>(&g_wt16[idx]) =
            make_uint2(*(unsigned*)&h0, *(unsigned*)&h1);
    }
}

// ---------------------------------------------------------------------------
// k1: gather + sparse kernel-point aggregation (round-5, proven).
// Per-segment: 1280 blocks x 8 warps = 10240 queries.
// ---------------------------------------------------------------------------
#define NW1 8
#define PLSZ (KNNB * KPN + 32)
__global__ __launch_bounds__(NW1 * 32) void k1_gather(
    const float* __restrict__ q_pts, const float* __restrict__ s_pts,
    const float* __restrict__ s_feats, const int* __restrict__ nidx,
    const float* __restrict__ kpts, int seg)
{
    __shared__ float  kp_s[KPN * 3];
    __shared__ float2 pair_s[NW1][PLSZ];

    const int tid  = threadIdx.x;
    const int wid  = tid >> 5;
    const int lane = tid & 31;
    const int qid  = seg * SEG_ROWS + blockIdx.x * NW1 + wid;

    if (tid < KPN * 3) kp_s[tid] = kpts[tid];
    __syncthreads();

    if (qid >= N_Q) return;        // padded queries: kf rows stay zero

    const int my_id = nidx[qid * KNNB + lane];

    const float qx = q_pts[qid * 3 + 0];
    const float qy = q_pts[qid * 3 + 1];
    const float qz = q_pts[qid * 3 + 2];
    float px, py, pz;
    if (my_id < M_S) {
        px = s_pts[my_id * 3 + 0];
        py = s_pts[my_id * 3 + 1];
        pz = s_pts[my_id * 3 + 2];
    } else { px = py = pz = 1e6f; }
    const float rx = px - qx, ry = py - qy, rz = pz - qz;

    float2* plist = pair_s[wid];
    const unsigned below = (1u << lane) - 1u;
    const float idf = __int_as_float(my_id);
    int cnt[KPN];
    int base = 0;
    #pragma unroll
    for (int e = 0; e < KPN; e++) {
        float dx = rx - kp_s[e * 3 + 0];
        float dy = ry - kp_s[e * 3 + 1];
        float dz = rz - kp_s[e * 3 + 2];
        float d2 = fmaf(dx, dx, fmaf(dy, dy, fmaf(dz, dz, 1e-8f)));
        float h  = 1.0f - sqrtf(d2) * KP_EXT_INV;
        unsigned m = __ballot_sync(0xffffffffu, h > 0.0f);
        int pos = (m & (1u << lane)) ? base + __popc(m & below)
                                     : KNNB * KPN + lane;
        plist[pos] = make_float2(h, idf);
        cnt[e] = __popc(m);
        base += cnt[e];
    }

    int idc = my_id < M_S ? my_id : 0;
    bool flag = (my_id < M_S) && (g_rs[idc] > 0.0f);
    unsigned bal = __ballot_sync(0xffffffffu, flag);
    if (lane == 0) {
        int c2 = __popc(bal);
        g_inv[qid] = 1.0f / (float)(c2 > 0 ? c2 : 1);
    }
    __syncwarp();

    const float* fb = s_feats + lane * 2;
    __half* dst = &g_kf16[(size_t)qid * KDIM + lane * 2];
    int base2 = 0;
    #pragma unroll
    for (int e = 0; e < KPN; e++) {
        int c = cnt[e];
        if (c) {                                 // warp-uniform
            unsigned long long acc = 0ull;
            const float2* pp = plist + base2;
            #pragma unroll 4
            for (int i = 0; i < c; i++) {
                float2 p = pp[i];                // LDS.64 broadcast
                int id = __float_as_int(p.y);
                unsigned long long hv, f2;
                asm("mov.b64 %0, {%1, %1};" : "=l"(hv) : "f"(p.x));
                f2 = *reinterpret_cast<const unsigned long long*>(
                         &fb[(size_t)id * CIN]);
                asm("fma.rn.f32x2 %0, %1, %2, %0;" : "+l"(acc) : "l"(f2), "l"(hv));
            }
            float lo, hi;
            asm("mov.b64 {%0, %1}, %2;" : "=f"(lo), "=f"(hi) : "l"(acc));
            *reinterpret_cast<__half2*>(&dst[e * CIN]) = __floats2half2_rn(lo, hi);
            base2 += c;
        }
    }
}

// ---------------------------------------------------------------------------
// k2: fp16 HMMA GEMM per segment (round-5 proven kernel; grid 80/seg).
// 128x128x64 tiles, 3-stage cp.async, ldmatrix, mma.m16n8k16.
// ---------------------------------------------------------------------------
#define KCH   64
#define NCH   (KDIM / KCH)     // 15
#define NSTG  3
#define FA_STAGE (BM * KCH)    // halfs
#define FB_STAGE (KCH * COUT)  // halfs

extern __shared__ __align__(16) unsigned char k2_dsm[];

__device__ __forceinline__ void cpa16s(unsigned dst, const __half* src)
{
    asm volatile("cp.async.cg.shared.global [%0], [%1], 16;\n" :: "r"(dst), "l"(src));
}

__global__ __launch_bounds__(256, 2) void k2_gemm(float* __restrict__ out, int seg)
{
    const unsigned as_u = (unsigned)__cvta_generic_to_shared(k2_dsm);
    const unsigned bs_u = as_u + NSTG * FA_STAGE * 2;

    const int tid  = threadIdx.x;
    const int wid  = tid >> 5;
    const int lane = tid & 31;
    const int g = lane >> 2;
    const int t = lane & 3;
    const int warp_m = wid & 1;
    const int warp_n = wid >> 1;
    const int m0 = seg * SEG_ROWS + blockIdx.x * BM;

    const __half* A = g_kf16;
    const __half* B = g_wt16;

    float c[4][4][4];
    #pragma unroll
    for (int mt = 0; mt < 4; mt++)
        #pragma unroll
        for (int nt = 0; nt < 4; nt++)
            #pragma unroll
            for (int r = 0; r < 4; r++) c[mt][nt][r] = 0.0f;

    auto load_tiles = [&](int stage, int k0) {
        unsigned as = as_u + stage * FA_STAGE * 2;
        unsigned bs = bs_u + stage * FB_STAGE * 2;
        #pragma unroll
        for (int it = 0; it < 4; it++) {
            int lin = tid + it * 256;
            int row = lin >> 3, gr = lin & 7;
            int gsw = gr ^ (row & 7);
            cpa16s(as + (row * 8 + gsw) * 16,
                   &A[(size_t)(m0 + row) * KDIM + k0 + gr * 8]);
        }
        #pragma unroll
        for (int it = 0; it < 4; it++) {
            int lin = tid + it * 256;
            int row = lin >> 4, gr = lin & 15;
            int gsw = gr ^ (row & 7);
            cpa16s(bs + (row * 16 + gsw) * 16,
                   &B[(k0 + row) * COUT + gr * 8]);
        }
    };

    load_tiles(0, 0);
    asm volatile("cp.async.commit_group;");
    load_tiles(1, KCH);
    asm volatile("cp.async.commit_group;");

    int cs = 0, ls = 2;
    for (int kc = 0; kc < NCH; kc++) {
        asm volatile("cp.async.wait_group 1;");
        __syncthreads();

        if (kc + 2 < NCH) {
            load_tiles(ls, (kc + 2) * KCH);
            ls = (ls == NSTG - 1) ? 0 : ls + 1;
        }
        asm volatile("cp.async.commit_group;");

        unsigned as = as_u + cs * FA_STAGE * 2;
        unsigned bs = bs_u + cs * FB_STAGE * 2;
        cs = (cs == NSTG - 1) ? 0 : cs + 1;

        #pragma unroll
        for (int kq = 0; kq < 4; kq++) {
            unsigned a_[4][4], b_[4][2];
            #pragma unroll
            for (int mt = 0; mt < 4; mt++) {
                int row = warp_m * 64 + mt * 16 + (lane & 15);
                int gr  = kq * 2 + (lane >> 4);
                unsigned addr = as + (row * 8 + (gr ^ (row & 7))) * 16;
                asm volatile(
                    "ldmatrix.sync.aligned.m8n8.x4.shared.b16 {%0,%1,%2,%3}, [%4];"
                    : "=r"(a_[mt][0]), "=r"(a_[mt][1]),
                      "=r"(a_[mt][2]), "=r"(a_[mt][3]) : "r"(addr));
            }
            #pragma unroll
            for (int cb = 0; cb < 2; cb++) {
                int row = kq * 16 + (lane & 15);
                int gr  = warp_n * 4 + cb * 2 + (lane >> 4);
                unsigned addr = bs + (row * 16 + (gr ^ (row & 7))) * 16;
                asm volatile(
                    "ldmatrix.sync.aligned.m8n8.x4.trans.shared.b16 {%0,%1,%2,%3}, [%4];"
                    : "=r"(b_[cb * 2][0]),     "=r"(b_[cb * 2][1]),
                      "=r"(b_[cb * 2 + 1][0]), "=r"(b_[cb * 2 + 1][1]) : "r"(addr));
            }
            #pragma unroll
            for (int mt = 0; mt < 4; mt++)
                #pragma unroll
                for (int nt = 0; nt < 4; nt++)
                    asm volatile(
                        "mma.sync.aligned.m16n8k16.row.col.f32.f16.f16.f32 "
                        "{%0,%1,%2,%3}, {%4,%5,%6,%7}, {%8,%9}, {%0,%1,%2,%3};"
                        : "+f"(c[mt][nt][0]), "+f"(c[mt][nt][1]),
                          "+f"(c[mt][nt][2]), "+f"(c[mt][nt][3])
                        : "r"(a_[mt][0]), "r"(a_[mt][1]),
                          "r"(a_[mt][2]), "r"(a_[mt][3]),
                          "r"(b_[nt][0]), "r"(b_[nt][1]));
        }
    }

    #pragma unroll
    for (int mt = 0; mt < 4; mt++) {
        int r0 = m0 + warp_m * 64 + mt * 16 + g;
        int r1 = r0 + 8;
        float inv0 = g_inv[r0];
        float inv1 = g_inv[r1];
        #pragma unroll
        for (int nt = 0; nt < 4; nt++) {
            int col = warp_n * 32 + nt * 8 + t * 2;
            if (r0 < N_Q)
                *(float2*)&out[(size_t)r0 * COUT + col] =
                    make_float2(c[mt][nt][0] * inv0, c[mt][nt][1] * inv0);
            if (r1 < N_Q)
                *(float2*)&out[(size_t)r1 * COUT + col] =
                    make_float2(c[mt][nt][2] * inv1, c[mt][nt][3] * inv1);
        }
    }
}

// ---------------------------------------------------------------------------
// Launch: segmented fork-join pipeline — k1 segments on the capture stream,
// k2 segments on a second stream gated by events; k2_seg_i overlaps
// k1_seg_{i+1}. Event record/wait are standard capture-graph fork-join edges.
// ---------------------------------------------------------------------------
extern "C" void kernel_launch(void* const* d_in, const int* in_sizes, int n_in,
                              void* d_out, int out_size)
{
    const float* q_pts   = (const float*)d_in[0];
    const float* s_pts   = (const float*)d_in[1];
    const float* s_feats = (const float*)d_in[2];
    const int*   nidx    = (const int*)  d_in[3];
    const float* W       = (const float*)d_in[4];
    const float* kpts    = (const float*)d_in[5];
    float* out = (float*)d_out;

    const int k2smem = NSTG * (FA_STAGE + FB_STAGE) * 2;   // 98304 B
    cudaFuncSetAttribute(k2_gemm,
        cudaFuncAttributeMaxDynamicSharedMemorySize, k2smem);

    cudaStream_t s2;
    cudaStreamCreate(&s2);

    k0_prep<<<391 + WCONV_BLKS, 256>>>(s_feats, W);

    cudaEvent_t ev[NSEG], evj;
    for (int i = 0; i < NSEG; i++) {
        k1_gather<<<SEG_ROWS / NW1, NW1 * 32>>>(
            q_pts, s_pts, s_feats, nidx, kpts, i);
        cudaEventCreateWithFlags(&ev[i], cudaEventDisableTiming);
        cudaEventRecord(ev[i], 0);
        cudaStreamWaitEvent(s2, ev[i], 0);
        k2_gemm<<<SEG_TILE, 256, k2smem, s2>>>(out, i);
    }
    cudaEventCreateWithFlags(&evj, cudaEventDisableTiming);
    cudaEventRecord(evj, s2);
    cudaStreamWaitEvent(0, evj, 0);    // join back to the capture stream
}

// round 16
// speedup vs baseline: 1.3911x; 1.3911x over previous
#include <cuda_runtime.h>
#include <cuda_fp16.h>
#include <cstdint>

#define N_Q   50000
#define M_S   50000
#define KNNB  32
#define KPN   15
#define CIN   64
#define COUT  128
#define KDIM  (KPN * CIN)      // 960
#define KP_EXT_INV (1.0f / 1.2f)

#define BM    128
#define BK2   64               // k-chunk (halfs) for fp16 GEMM
#define NKC   (KDIM / BK2)     // 15
#define M_PAD (391 * BM)       // 50048

// Scratch (zero-initialized device globals)
__device__ __half g_kf16[(size_t)M_PAD * KDIM];   // fp16 kernel_feats
__device__ __half g_wt16[KDIM * COUT];            // fp16 weights
__device__ float  g_inv[M_PAD];
__device__ float  g_rs[M_S];                      // per-support-row channel sum

// ---------------------------------------------------------------------------
// k0a: rowsum of s_feats per support point (validity test)
// ---------------------------------------------------------------------------
__global__ __launch_bounds__(256) void k0a_rowsum(const float* __restrict__ sf)
{
    int wid = threadIdx.x >> 5, lane = threadIdx.x & 31;
    int row = blockIdx.x * 8 + wid;
    float2 v = *(const float2*)&sf[(size_t)row * CIN + lane * 2];
    float s = v.x + v.y;
    #pragma unroll
    for (int off = 16; off; off >>= 1) s += __shfl_xor_sync(0xffffffffu, s, off);
    if (lane == 0) g_rs[row] = s;
}

// ---------------------------------------------------------------------------
// k0b: W -> fp16
// ---------------------------------------------------------------------------
__global__ __launch_bounds__(256) void k0b_cvtw(const float* __restrict__ W)
{
    int i = (blockIdx.x * 256 + threadIdx.x) * 4;     // grid covers exactly
    float4 v = *(const float4*)&W[i];
    __half2 h0 = __floats2half2_rn(v.x, v.y);
    __half2 h1 = __floats2half2_rn(v.z, v.w);
    *reinterpret_cast<uint2*>(&g_wt16[i]) =
        make_uint2(*(unsigned*)&h0, *(unsigned*)&h1);
}

// ---------------------------------------------------------------------------
// k1: gather + sparse kernel-point aggregation.  Warp per query.
// Pair list stores (h, support_id); aggregation reads features directly via
// LDG (L1-cached across e-groups). No smem staging, no cp.async, branch-lean.
// ---------------------------------------------------------------------------
#define NW1 8
#define PLSZ (KNNB * KPN + 32)     // 480 pairs max + 32 dump slots
__global__ __launch_bounds__(NW1 * 32) void k1_gather(
    const float* __restrict__ q_pts, const float* __restrict__ s_pts,
    const float* __restrict__ s_feats, const int* __restrict__ nidx,
    const float* __restrict__ kpts)
{
    __shared__ float  kp_s[KPN * 3];
    __shared__ float2 pair_s[NW1][PLSZ];     // (h, id) list

    const int tid  = threadIdx.x;
    const int wid  = tid >> 5;
    const int lane = tid & 31;
    const int qid  = blockIdx.x * NW1 + wid;        // grid = 6250 exact

    if (tid < KPN * 3) kp_s[tid] = kpts[tid];
    __syncthreads();

    const int my_id = nidx[qid * KNNB + lane];

    // ---- geometry: lane = neighbor; build (h, id) pair list grouped by e ----
    const float qx = q_pts[qid * 3 + 0];
    const float qy = q_pts[qid * 3 + 1];
    const float qz = q_pts[qid * 3 + 2];
    float px, py, pz;
    if (my_id < M_S) {
        px = s_pts[my_id * 3 + 0];
        py = s_pts[my_id * 3 + 1];
        pz = s_pts[my_id * 3 + 2];
    } else { px = py = pz = 1e6f; }   // shadow: h always <= 0, never listed
    const float rx = px - qx, ry = py - qy, rz = pz - qz;

    float2* plist = pair_s[wid];
    const unsigned below = (1u << lane) - 1u;
    const float idf = __int_as_float(my_id);
    int cnt[KPN];
    int base = 0;
    #pragma unroll
    for (int e = 0; e < KPN; e++) {
        float dx = rx - kp_s[e * 3 + 0];
        float dy = ry - kp_s[e * 3 + 1];
        float dz = rz - kp_s[e * 3 + 2];
        float d2 = fmaf(dx, dx, fmaf(dy, dy, fmaf(dz, dz, 1e-8f)));
        float h  = 1.0f - sqrtf(d2) * KP_EXT_INV;
        unsigned m = __ballot_sync(0xffffffffu, h > 0.0f);
        // unconditional store: inactive lanes hit dump slots (SEL, no branch)
        int pos = (m & (1u << lane)) ? base + __popc(m & below)
                                     : KNNB * KPN + lane;
        plist[pos] = make_float2(h, idf);
        cnt[e] = __popc(m);
        base += cnt[e];
    }

    // ---- validity count ----
    int idc = my_id < M_S ? my_id : 0;
    bool flag = (my_id < M_S) && (g_rs[idc] > 0.0f);
    unsigned bal = __ballot_sync(0xffffffffu, flag);
    if (lane == 0) {
        int c2 = __popc(bal);
        g_inv[qid] = 1.0f / (float)(c2 > 0 ? c2 : 1);
    }
    __syncwarp();

    // ---- aggregation: lane = channel-pair; LDG features (L1-resident) ----
    const float* fb = s_feats + lane * 2;
    __half* dst = &g_kf16[(size_t)qid * KDIM + lane * 2];
    int base2 = 0;
    #pragma unroll
    for (int e = 0; e < KPN; e++) {
        int c = cnt[e];
        if (c) {                                 // warp-uniform
            unsigned long long acc = 0ull;
            const float2* pp = plist + base2;
            #pragma unroll 4
            for (int i = 0; i < c; i++) {
                float2 p = pp[i];                // LDS.64 broadcast
                int id = __float_as_int(p.y);
                unsigned long long hv, f2;
                asm("mov.b64 %0, {%1, %1};" : "=l"(hv) : "f"(p.x));
                f2 = *reinterpret_cast<const unsigned long long*>(
                         &fb[(size_t)id * CIN]);
                asm("fma.rn.f32x2 %0, %1, %2, %0;" : "+l"(acc) : "l"(f2), "l"(hv));
            }
            float lo, hi;
            asm("mov.b64 {%0, %1}, %2;" : "=f"(lo), "=f"(hi) : "l"(acc));
            *reinterpret_cast<__half2*>(&dst[e * CIN]) = __floats2half2_rn(lo, hi);
            base2 += c;
        }
    }
}

// ---------------------------------------------------------------------------
// k2: fp16 tensor-core GEMM  C[50048,128] = A[50048,960] @ B[960,128],
// row-scaled by g_inv.  128x128x64 tiles, 3-stage cp.async, ldmatrix,
// XOR-swizzled smem, mma.m16n8k16.f16 with fp32 accumulate.
// ---------------------------------------------------------------------------
#define ASTAGE (BM * BK2)        // halfs per A stage (16 KB)
#define BSTAGE (BK2 * COUT)      // halfs per B stage (16 KB)
#define NSTG   3

extern __shared__ __half k2_smem[];

__device__ __forceinline__ void cpa16s(unsigned dst, const __half* src)
{
    asm volatile("cp.async.cg.shared.global [%0], [%1], 16;\n" :: "r"(dst), "l"(src));
}

__global__ __launch_bounds__(256, 2) void k2_gemm(float* __restrict__ out)
{
    const unsigned as_u = (unsigned)__cvta_generic_to_shared(k2_smem);
    const unsigned bs_u = as_u + NSTG * ASTAGE * 2;

    const int tid  = threadIdx.x;
    const int wid  = tid >> 5;
    const int lane = tid & 31;
    const int g = lane >> 2;          // 0..7
    const int t = lane & 3;           // 0..3
    const int warp_m = wid & 1;       // 64 rows each
    const int warp_n = wid >> 1;      // 32 cols each
    const int m0 = blockIdx.x * BM;

    const __half* A = g_kf16;
    const __half* B = g_wt16;

    float c[4][4][4];
    #pragma unroll
    for (int mt = 0; mt < 4; mt++)
        #pragma unroll
        for (int nt = 0; nt < 4; nt++)
            #pragma unroll
            for (int r = 0; r < 4; r++) c[mt][nt][r] = 0.0f;

    auto load_tiles = [&](int stage, int k0) {
        unsigned as = as_u + stage * ASTAGE * 2;
        unsigned bs = bs_u + stage * BSTAGE * 2;
        #pragma unroll
        for (int it = 0; it < 4; it++) {
            int lin = tid + it * 256;            // 0..1023
            int row = lin >> 3, gr = lin & 7;
            int gsw = gr ^ (row & 7);
            cpa16s(as + (row * 8 + gsw) * 16,
                   &A[(size_t)(m0 + row) * KDIM + k0 + gr * 8]);
        }
        #pragma unroll
        for (int it = 0; it < 4; it++) {
            int lin = tid + it * 256;
            int row = lin >> 4, gr = lin & 15;
            int gsw = gr ^ (row & 7);
            cpa16s(bs + (row * 16 + gsw) * 16,
                   &B[(k0 + row) * COUT + gr * 8]);
        }
    };

    load_tiles(0, 0);
    asm volatile("cp.async.commit_group;");
    load_tiles(1, BK2);
    asm volatile("cp.async.commit_group;");

    int cs = 0;                 // compute stage
    int ls = 2;                 // next load stage
    for (int kc = 0; kc < NKC; kc++) {
        asm volatile("cp.async.wait_group 1;");
        __syncthreads();

        if (kc + 2 < NKC) {
            load_tiles(ls, (kc + 2) * BK2);
            ls = (ls == NSTG - 1) ? 0 : ls + 1;
        }
        asm volatile("cp.async.commit_group;");

        unsigned as = as_u + cs * ASTAGE * 2;
        unsigned bs = bs_u + cs * BSTAGE * 2;
        cs = (cs == NSTG - 1) ? 0 : cs + 1;

        #pragma unroll
        for (int kq = 0; kq < 4; kq++) {        // 4 k16-steps per chunk
            unsigned a_[4][4], b_[4][2];
            #pragma unroll
            for (int mt = 0; mt < 4; mt++) {
                int row = warp_m * 64 + mt * 16 + (lane & 15);
                int gr  = kq * 2 + (lane >> 4);
                unsigned addr = as + (row * 8 + (gr ^ (row & 7))) * 16;
                asm volatile(
                    "ldmatrix.sync.aligned.m8n8.x4.shared.b16 {%0,%1,%2,%3}, [%4];"
                    : "=r"(a_[mt][0]), "=r"(a_[mt][1]),
                      "=r"(a_[mt][2]), "=r"(a_[mt][3]) : "r"(addr));
            }
            #pragma unroll
            for (int cb = 0; cb < 2; cb++) {
                int row = kq * 16 + (lane & 15);
                int gr  = warp_n * 4 + cb * 2 + (lane >> 4);
                unsigned addr = bs + (row * 16 + (gr ^ (row & 7))) * 16;
                asm volatile(
                    "ldmatrix.sync.aligned.m8n8.x4.trans.shared.b16 {%0,%1,%2,%3}, [%4];"
                    : "=r"(b_[cb * 2][0]),     "=r"(b_[cb * 2][1]),
                      "=r"(b_[cb * 2 + 1][0]), "=r"(b_[cb * 2 + 1][1]) : "r"(addr));
            }
            #pragma unroll
            for (int mt = 0; mt < 4; mt++)
                #pragma unroll
                for (int nt = 0; nt < 4; nt++)
                    asm volatile(
                        "mma.sync.aligned.m16n8k16.row.col.f32.f16.f16.f32 "
                        "{%0,%1,%2,%3}, {%4,%5,%6,%7}, {%8,%9}, {%0,%1,%2,%3};"
                        : "+f"(c[mt][nt][0]), "+f"(c[mt][nt][1]),
                          "+f"(c[mt][nt][2]), "+f"(c[mt][nt][3])
                        : "r"(a_[mt][0]), "r"(a_[mt][1]),
                          "r"(a_[mt][2]), "r"(a_[mt][3]),
                          "r"(b_[nt][0]), "r"(b_[nt][1]));
        }
    }

    // epilogue: scale by g_inv, store
    #pragma unroll
    for (int mt = 0; mt < 4; mt++) {
        int r0 = m0 + warp_m * 64 + mt * 16 + g;
        int r1 = r0 + 8;
        float inv0 = g_inv[r0];
        float inv1 = g_inv[r1];
        #pragma unroll
        for (int nt = 0; nt < 4; nt++) {
            int col = warp_n * 32 + nt * 8 + t * 2;
            if (r0 < N_Q)
                *(float2*)&out[(size_t)r0 * COUT + col] =
                    make_float2(c[mt][nt][0] * inv0, c[mt][nt][1] * inv0);
            if (r1 < N_Q)
                *(float2*)&out[(size_t)r1 * COUT + col] =
                    make_float2(c[mt][nt][2] * inv1, c[mt][nt][3] * inv1);
        }
    }
}

// ---------------------------------------------------------------------------
extern "C" void kernel_launch(void* const* d_in, const int* in_sizes, int n_in,
                              void* d_out, int out_size)
{
    const float* q_pts   = (const float*)d_in[0];
    const float* s_pts   = (const float*)d_in[1];
    const float* s_feats = (const float*)d_in[2];
    const int*   nidx    = (const int*)  d_in[3];
    const float* W       = (const float*)d_in[4];
    const float* kpts    = (const float*)d_in[5];
    float* out = (float*)d_out;

    const int k2smem = NSTG * (ASTAGE + BSTAGE) * (int)sizeof(__half);  // 98304 B
    cudaFuncSetAttribute(k2_gemm, cudaFuncAttributeMaxDynamicSharedMemorySize, k2smem);

    k0a_rowsum<<<M_S / 8, 256>>>(s_feats);
    k0b_cvtw<<<(KDIM * COUT / 4) / 256, 256>>>(W);
    k1_gather<<<N_Q / NW1, NW1 * 32>>>(q_pts, s_pts, s_feats, nidx, kpts);
    k2_gemm<<<M_PAD / BM, 256, k2smem>>>(out);
}

// round 17
// speedup vs baseline: 1.4572x; 1.0476x over previous
#include <cuda_runtime.h>
#include <cuda_fp16.h>
#include <cstdint>

#define N_Q   50000
#define M_S   50000
#define KNNB  32
#define KPN   15
#define CIN   64
#define COUT  128
#define KDIM  (KPN * CIN)      // 960
#define KP_EXT_INV (1.0f / 1.2f)

#define BM    128
#define BK2   64               // k-chunk (halfs) for fp16 GEMM
#define NKC   (KDIM / BK2)     // 15
#define M_PAD (391 * BM)       // 50048

#define RS_BLKS    782                          // ceil(50000/64) rows blocks
#define WCONV_BLKS ((KDIM * COUT) / 4 / 256)    // 120: 120*256*4 = 122880 exact

// Scratch (zero-initialized device globals)
__device__ __half g_kf16[(size_t)M_PAD * KDIM];   // fp16 kernel_feats
__device__ __half g_wt16[KDIM * COUT];            // fp16 weights
__device__ float  g_inv[M_PAD];
__device__ float  g_rs[M_S];                      // per-support-row channel sum

// ---------------------------------------------------------------------------
// k0: blocks 0..781: rowsum of s_feats — warp per 8 rows, lane = (row, qtr),
//     4 x LDG.128 per lane (high MLP), 2-shfl reduce over 4 lanes.
//     blocks 782..901: W -> fp16 (exact cover of 960*128 elements)
// ---------------------------------------------------------------------------
__global__ __launch_bounds__(256) void k0_prep(
    const float* __restrict__ sf, const float* __restrict__ W)
{
    int b = blockIdx.x;
    if (b < RS_BLKS) {
        int wid  = threadIdx.x >> 5;
        int lane = threadIdx.x & 31;
        int rloc = lane >> 2;            // 0..7 row within warp group
        int part = lane & 3;             // 0..3 channel quarter
        int row  = b * 64 + wid * 8 + rloc;
        if (row < M_S) {
            const float4* p = (const float4*)&sf[(size_t)row * CIN];
            float s = 0.0f;
            #pragma unroll
            for (int i = 0; i < 4; i++) {          // 4 independent LDG.128
                float4 v = p[part + i * 4];
                s += (v.x + v.y) + (v.z + v.w);
            }
            s += __shfl_xor_sync(0xffffffffu, s, 1);
            s += __shfl_xor_sync(0xffffffffu, s, 2);
            if (part == 0) g_rs[row] = s;
        }
    } else {
        int idx = ((b - RS_BLKS) * 256 + threadIdx.x) * 4;   // < 960*128 exact
        float4 v = *(const float4*)&W[idx];
        __half2 h0 = __floats2half2_rn(v.x, v.y);
        __half2 h1 = __floats2half2_rn(v.z, v.w);
        *reinterpret_cast<uint2*>(&g_wt16[idx]) =
            make_uint2(*(unsigned*)&h0, *(unsigned*)&h1);
    }
}

// ---------------------------------------------------------------------------
// k1: gather + sparse kernel-point aggregation (champion, proven ~41us).
// Warp per query; (h, id) pair list grouped by kernel point; f32 LDG gather.
// ---------------------------------------------------------------------------
#define NW1 8
#define PLSZ (KNNB * KPN + 32)     // 480 pairs max + 32 dump slots
__global__ __launch_bounds__(NW1 * 32) void k1_gather(
    const float* __restrict__ q_pts, const float* __restrict__ s_pts,
    const float* __restrict__ s_feats, const int* __restrict__ nidx,
    const float* __restrict__ kpts)
{
    __shared__ float  kp_s[KPN * 3];
    __shared__ float2 pair_s[NW1][PLSZ];     // (h, id) list

    const int tid  = threadIdx.x;
    const int wid  = tid >> 5;
    const int lane = tid & 31;
    const int qid  = blockIdx.x * NW1 + wid;        // grid = 6250 exact

    if (tid < KPN * 3) kp_s[tid] = kpts[tid];
    __syncthreads();

    const int my_id = nidx[qid * KNNB + lane];

    const float qx = q_pts[qid * 3 + 0];
    const float qy = q_pts[qid * 3 + 1];
    const float qz = q_pts[qid * 3 + 2];
    float px, py, pz;
    if (my_id < M_S) {
        px = s_pts[my_id * 3 + 0];
        py = s_pts[my_id * 3 + 1];
        pz = s_pts[my_id * 3 + 2];
    } else { px = py = pz = 1e6f; }   // shadow: h always <= 0, never listed
    const float rx = px - qx, ry = py - qy, rz = pz - qz;

    float2* plist = pair_s[wid];
    const unsigned below = (1u << lane) - 1u;
    const float idf = __int_as_float(my_id);
    int cnt[KPN];
    int base = 0;
    #pragma unroll
    for (int e = 0; e < KPN; e++) {
        float dx = rx - kp_s[e * 3 + 0];
        float dy = ry - kp_s[e * 3 + 1];
        float dz = rz - kp_s[e * 3 + 2];
        float d2 = fmaf(dx, dx, fmaf(dy, dy, fmaf(dz, dz, 1e-8f)));
        float h  = 1.0f - sqrtf(d2) * KP_EXT_INV;
        unsigned m = __ballot_sync(0xffffffffu, h > 0.0f);
        int pos = (m & (1u << lane)) ? base + __popc(m & below)
                                     : KNNB * KPN + lane;
        plist[pos] = make_float2(h, idf);
        cnt[e] = __popc(m);
        base += cnt[e];
    }

    int idc = my_id < M_S ? my_id : 0;
    bool flag = (my_id < M_S) && (g_rs[idc] > 0.0f);
    unsigned bal = __ballot_sync(0xffffffffu, flag);
    if (lane == 0) {
        int c2 = __popc(bal);
        g_inv[qid] = 1.0f / (float)(c2 > 0 ? c2 : 1);
    }
    __syncwarp();

    const float* fb = s_feats + lane * 2;
    __half* dst = &g_kf16[(size_t)qid * KDIM + lane * 2];
    int base2 = 0;
    #pragma unroll
    for (int e = 0; e < KPN; e++) {
        int c = cnt[e];
        if (c) {                                 // warp-uniform
            unsigned long long acc = 0ull;
            const float2* pp = plist + base2;
            #pragma unroll 4
            for (int i = 0; i < c; i++) {
                float2 p = pp[i];                // LDS.64 broadcast
                int id = __float_as_int(p.y);
                unsigned long long hv, f2;
                asm("mov.b64 %0, {%1, %1};" : "=l"(hv) : "f"(p.x));
                f2 = *reinterpret_cast<const unsigned long long*>(
                         &fb[(size_t)id * CIN]);
                asm("fma.rn.f32x2 %0, %1, %2, %0;" : "+l"(acc) : "l"(f2), "l"(hv));
            }
            float lo, hi;
            asm("mov.b64 {%0, %1}, %2;" : "=f"(lo), "=f"(hi) : "l"(acc));
            *reinterpret_cast<__half2*>(&dst[e * CIN]) = __floats2half2_rn(lo, hi);
            base2 += c;
        }
    }
}

// ---------------------------------------------------------------------------
// k2: fp16 tensor-core GEMM (champion, proven 39.5us = mma.sync issue wall).
// 128x128x64 tiles, 3-stage cp.async, ldmatrix, mma.m16n8k16, scaled epilogue.
// ---------------------------------------------------------------------------
#define ASTAGE (BM * BK2)        // halfs per A stage (16 KB)
#define BSTAGE (BK2 * COUT)      // halfs per B stage (16 KB)
#define NSTG   3

extern __shared__ __half k2_smem[];

__device__ __forceinline__ void cpa16s(unsigned dst, const __half* src)
{
    asm volatile("cp.async.cg.shared.global [%0], [%1], 16;\n" :: "r"(dst), "l"(src));
}

__global__ __launch_bounds__(256, 2) void k2_gemm(float* __restrict__ out)
{
    const unsigned as_u = (unsigned)__cvta_generic_to_shared(k2_smem);
    const unsigned bs_u = as_u + NSTG * ASTAGE * 2;

    const int tid  = threadIdx.x;
    const int wid  = tid >> 5;
    const int lane = tid & 31;
    const int g = lane >> 2;          // 0..7
    const int t = lane & 3;           // 0..3
    const int warp_m = wid & 1;       // 64 rows each
    const int warp_n = wid >> 1;      // 32 cols each
    const int m0 = blockIdx.x * BM;

    const __half* A = g_kf16;
    const __half* B = g_wt16;

    float c[4][4][4];
    #pragma unroll
    for (int mt = 0; mt < 4; mt++)
        #pragma unroll
        for (int nt = 0; nt < 4; nt++)
            #pragma unroll
            for (int r = 0; r < 4; r++) c[mt][nt][r] = 0.0f;

    auto load_tiles = [&](int stage, int k0) {
        unsigned as = as_u + stage * ASTAGE * 2;
        unsigned bs = bs_u + stage * BSTAGE * 2;
        #pragma unroll
        for (int it = 0; it < 4; it++) {
            int lin = tid + it * 256;            // 0..1023
            int row = lin >> 3, gr = lin & 7;
            int gsw = gr ^ (row & 7);
            cpa16s(as + (row * 8 + gsw) * 16,
                   &A[(size_t)(m0 + row) * KDIM + k0 + gr * 8]);
        }
        #pragma unroll
        for (int it = 0; it < 4; it++) {
            int lin = tid + it * 256;
            int row = lin >> 4, gr = lin & 15;
            int gsw = gr ^ (row & 7);
            cpa16s(bs + (row * 16 + gsw) * 16,
                   &B[(k0 + row) * COUT + gr * 8]);
        }
    };

    load_tiles(0, 0);
    asm volatile("cp.async.commit_group;");
    load_tiles(1, BK2);
    asm volatile("cp.async.commit_group;");

    int cs = 0;                 // compute stage
    int ls = 2;                 // next load stage
    for (int kc = 0; kc < NKC; kc++) {
        asm volatile("cp.async.wait_group 1;");
        __syncthreads();

        if (kc + 2 < NKC) {
            load_tiles(ls, (kc + 2) * BK2);
            ls = (ls == NSTG - 1) ? 0 : ls + 1;
        }
        asm volatile("cp.async.commit_group;");

        unsigned as = as_u + cs * ASTAGE * 2;
        unsigned bs = bs_u + cs * BSTAGE * 2;
        cs = (cs == NSTG - 1) ? 0 : cs + 1;

        #pragma unroll
        for (int kq = 0; kq < 4; kq++) {        // 4 k16-steps per chunk
            unsigned a_[4][4], b_[4][2];
            #pragma unroll
            for (int mt = 0; mt < 4; mt++) {
                int row = warp_m * 64 + mt * 16 + (lane & 15);
                int gr  = kq * 2 + (lane >> 4);
                unsigned addr = as + (row * 8 + (gr ^ (row & 7))) * 16;
                asm volatile(
                    "ldmatrix.sync.aligned.m8n8.x4.shared.b16 {%0,%1,%2,%3}, [%4];"
                    : "=r"(a_[mt][0]), "=r"(a_[mt][1]),
                      "=r"(a_[mt][2]), "=r"(a_[mt][3]) : "r"(addr));
            }
            #pragma unroll
            for (int cb = 0; cb < 2; cb++) {
                int row = kq * 16 + (lane & 15);
                int gr  = warp_n * 4 + cb * 2 + (lane >> 4);
                unsigned addr = bs + (row * 16 + (gr ^ (row & 7))) * 16;
                asm volatile(
                    "ldmatrix.sync.aligned.m8n8.x4.trans.shared.b16 {%0,%1,%2,%3}, [%4];"
                    : "=r"(b_[cb * 2][0]),     "=r"(b_[cb * 2][1]),
                      "=r"(b_[cb * 2 + 1][0]), "=r"(b_[cb * 2 + 1][1]) : "r"(addr));
            }
            #pragma unroll
            for (int mt = 0; mt < 4; mt++)
                #pragma unroll
                for (int nt = 0; nt < 4; nt++)
                    asm volatile(
                        "mma.sync.aligned.m16n8k16.row.col.f32.f16.f16.f32 "
                        "{%0,%1,%2,%3}, {%4,%5,%6,%7}, {%8,%9}, {%0,%1,%2,%3};"
                        : "+f"(c[mt][nt][0]), "+f"(c[mt][nt][1]),
                          "+f"(c[mt][nt][2]), "+f"(c[mt][nt][3])
                        : "r"(a_[mt][0]), "r"(a_[mt][1]),
                          "r"(a_[mt][2]), "r"(a_[mt][3]),
                          "r"(b_[nt][0]), "r"(b_[nt][1]));
        }
    }

    // epilogue: scale by g_inv, store
    #pragma unroll
    for (int mt = 0; mt < 4; mt++) {
        int r0 = m0 + warp_m * 64 + mt * 16 + g;
        int r1 = r0 + 8;
        float inv0 = g_inv[r0];
        float inv1 = g_inv[r1];
        #pragma unroll
        for (int nt = 0; nt < 4; nt++) {
            int col = warp_n * 32 + nt * 8 + t * 2;
            if (r0 < N_Q)
                *(float2*)&out[(size_t)r0 * COUT + col] =
                    make_float2(c[mt][nt][0] * inv0, c[mt][nt][1] * inv0);
            if (r1 < N_Q)
                *(float2*)&out[(size_t)r1 * COUT + col] =
                    make_float2(c[mt][nt][2] * inv1, c[mt][nt][3] * inv1);
        }
    }
}

// ---------------------------------------------------------------------------
extern "C" void kernel_launch(void* const* d_in, const int* in_sizes, int n_in,
                              void* d_out, int out_size)
{
    const float* q_pts   = (const float*)d_in[0];
    const float* s_pts   = (const float*)d_in[1];
    const float* s_feats = (const float*)d_in[2];
    const int*   nidx    = (const int*)  d_in[3];
    const float* W       = (const float*)d_in[4];
    const float* kpts    = (const float*)d_in[5];
    float* out = (float*)d_out;

    const int k2smem = NSTG * (ASTAGE + BSTAGE) * (int)sizeof(__half);  // 98304 B
    cudaFuncSetAttribute(k2_gemm, cudaFuncAttributeMaxDynamicSharedMemorySize, k2smem);

    k0_prep<<<RS_BLKS + WCONV_BLKS, 256>>>(s_feats, W);
    k1_gather<<<N_Q / NW1, NW1 * 32>>>(q_pts, s_pts, s_feats, nidx, kpts);
    k2_gemm<<<M_PAD / BM, 256, k2smem>>>(out);
}